// round 2
// baseline (speedup 1.0000x reference)
#include <cuda_runtime.h>
#include <cstdint>

// Problem constants
#define NB   1024   // batch
#define CIN  64     // input channels (2 groups of 32)
#define HH   28
#define WW   28
#define LL   32     // effective channels
#define KK   288    // GEMM K = 32*3*3  (kk = l*9 + j*3 + k, matches W flattening)
#define II   128    // output channels
#define PAIRS (NB*HH)   // 28672 (n,h) pairs

#define WS_FLOATS (KK*II)          // 36864 floats = 147456 B
#define WS_BYTES  (WS_FLOATS*4)
#define T6_ELEMS  (KK*WW)          // 8064 ull (each holds duplicated f32x2)
#define T6_BYTES  (T6_ELEMS*8)     // 64512 B
#define SMEM_TOTAL (WS_BYTES + T6_BYTES)  // 211968 B

__device__ __forceinline__ unsigned long long fma2(unsigned long long a,
                                                   unsigned long long b,
                                                   unsigned long long c) {
    unsigned long long d;
    asm("fma.rn.f32x2 %0, %1, %2, %3;" : "=l"(d) : "l"(a), "l"(b), "l"(c));
    return d;
}

__device__ __forceinline__ float ull_lo(unsigned long long v) {
    return __uint_as_float((unsigned)(v & 0xffffffffull));
}
__device__ __forceinline__ float ull_hi(unsigned long long v) {
    return __uint_as_float((unsigned)(v >> 32));
}

__global__ __launch_bounds__(128, 1)
void shiftconv_kernel(const float* __restrict__ x,
                      const float* __restrict__ Wg,
                      float* __restrict__ out) {
    extern __shared__ char smem[];
    float* ws = reinterpret_cast<float*>(smem);                       // [KK][II]
    unsigned long long* t6s =
        reinterpret_cast<unsigned long long*>(smem + WS_BYTES);       // [KK][WW] dup f32x2

    const int tid = threadIdx.x;

    // ---- Phase A: stage weights into smem (verbatim copy; layout already [kk][i]) ----
    {
        const float4* src = reinterpret_cast<const float4*>(Wg);
        float4* dst = reinterpret_cast<float4*>(ws);
        #pragma unroll 4
        for (int idx = tid; idx < WS_FLOATS / 4; idx += 128)
            dst[idx] = src[idx];
    }

    const int iq = tid & 31;          // 32 i-groups
    const int wq = tid >> 5;          // 4 w-groups
    const int i0 = iq * 4;
    const int wbase = wq * 7;

    // ---- Persistent loop over (n,h) pairs ----
    for (int p = blockIdx.x; p < PAIRS; p += gridDim.x) {
        const int n = p / HH;
        const int h = p - n * HH;

        __syncthreads();   // previous GEMM readers done (also orders Phase A on iter 0)

        // ---- Phase B: build T6 tile: t6s[kk*28 + w] = dup(t6[n,l,h+j-1,k,w]) ----
        // t6 = t2(l, w) + t2(32+l, (w-1) mod 28)
        // t2(c, ww) = x[n,c,h',(ww+k-2) mod 28] if 0 <= ww+k-1 < 28 else 0
        {
            int e = tid;
            #pragma unroll 7
            for (int it = 0; it < T6_ELEMS / 128; ++it, e += 128) {  // 63 iters
                const int kk = e / WW;
                const int w  = e - kk * WW;
                const int l  = kk / 9;
                const int r  = kk - l * 9;
                const int j  = r / 3;
                const int k  = r - j * 3;
                const int hp = h + j - 1;
                float v = 0.0f;
                if ((unsigned)hp < (unsigned)HH) {
                    const size_t rowbase = (((size_t)n * CIN + l) * HH + hp) * WW;
                    const int u1 = w + k - 1;
                    if ((unsigned)u1 < (unsigned)WW) {
                        const int c1 = (u1 == 0) ? (WW - 1) : (u1 - 1);
                        v += x[rowbase + c1];
                    }
                    const int w2 = (w == 0) ? (WW - 1) : (w - 1);
                    const int u2 = w2 + k - 1;
                    if ((unsigned)u2 < (unsigned)WW) {
                        const int c2 = (u2 == 0) ? (WW - 1) : (u2 - 1);
                        v += x[rowbase + (size_t)32 * HH * WW + c2];
                    }
                }
                const unsigned ui = __float_as_uint(v);
                t6s[e] = ((unsigned long long)ui << 32) | (unsigned long long)ui;
            }
        }

        __syncthreads();

        // ---- Phase C: GEMM  C[28 x 128] = T6[28 x 288] * W[288 x 128] ----
        unsigned long long acc[7][2];
        #pragma unroll
        for (int t = 0; t < 7; ++t) { acc[t][0] = 0ull; acc[t][1] = 0ull; }

        #pragma unroll 4
        for (int kk = 0; kk < KK; ++kk) {
            const ulonglong2 wv =
                *reinterpret_cast<const ulonglong2*>(&ws[kk * II + i0]); // 4 weights
            const unsigned long long* trow = &t6s[kk * WW + wbase];
            #pragma unroll
            for (int t = 0; t < 7; ++t) {
                const unsigned long long b = trow[t];      // dup f32x2, smem broadcast
                acc[t][0] = fma2(b, wv.x, acc[t][0]);
                acc[t][1] = fma2(b, wv.y, acc[t][1]);
            }
        }

        // ---- Epilogue: out[n, i, h, w], row-major ----
        const size_t obase = (((size_t)n * II + i0) * HH + h) * WW;
        #pragma unroll
        for (int t = 0; t < 7; ++t) {
            const int w = wbase + t;
            out[obase + w]                = ull_lo(acc[t][0]);
            out[obase + 1 * HH * WW + w]  = ull_hi(acc[t][0]);
            out[obase + 2 * HH * WW + w]  = ull_lo(acc[t][1]);
            out[obase + 3 * HH * WW + w]  = ull_hi(acc[t][1]);
        }
    }
}

extern "C" void kernel_launch(void* const* d_in, const int* in_sizes, int n_in,
                              void* d_out, int out_size) {
    const float* x  = (const float*)d_in[0];   // (1024,64,28,28) f32
    const float* Wg = (const float*)d_in[1];   // (32,3,3,128)   f32
    float* out = (float*)d_out;                // (1024,128,28,28) f32

    cudaFuncSetAttribute(shiftconv_kernel,
                         cudaFuncAttributeMaxDynamicSharedMemorySize, SMEM_TOTAL);
    shiftconv_kernel<<<592, 128, SMEM_TOTAL>>>(x, Wg, out);
}

// round 4
// speedup vs baseline: 6.8351x; 6.8351x over previous
#include <cuda_runtime.h>
#include <cstdint>

// ================= problem constants =================
#define NB   1024
#define IIC  128
#define KKT  288            // 9 chunks * 32
#define TILES_PER_N 7
#define NTILES (NB*TILES_PER_N)     // 7168
#define GRID_MAIN 152

// ================= scratch =================
// g_R[(n*28+h')][idx 0..31][l 0..31]  (tf32-rounded floats)
#define R_ELEMS ((size_t)NB*28*32*32)
__device__ float g_R[R_ELEMS];   // 117 MB

// ================= main smem layout =================
// WS: weights, fragment-ready: float4 per (S=0..35, mt=0..7, lane=0..31)
#define WS_OFF    0
#define WS_BYTES  (36*8*32*16)          // 147456
// ACT: activations chunk, fragment-ready: float2 per (s=0..3, nt=0..15, lane)
#define ACT_BYTES (4*16*32*8)           // 16384
#define ACT0_OFF  (WS_OFF + WS_BYTES)   // 147456
#define ACT1_OFF  (ACT0_OFF + ACT_BYTES)// 163840
#define OFF9_OFF  (ACT1_OFF + ACT_BYTES)// 180224   int off9[9][128]
#define SM_TOTAL  (OFF9_OFF + 9*128*4)  // 184832

__device__ __forceinline__ uint32_t f2tf32(float v) {
    uint32_t o; asm("cvt.rna.tf32.f32 %0, %1;" : "=r"(o) : "f"(v)); return o;
}

__device__ __forceinline__ void mma_tf32(float4& d, const uint4& a, const uint2& b) {
    asm volatile(
        "mma.sync.aligned.m16n8k8.row.col.f32.tf32.tf32.f32 "
        "{%0,%1,%2,%3}, {%4,%5,%6,%7}, {%8,%9}, {%0,%1,%2,%3};"
        : "+f"(d.x), "+f"(d.y), "+f"(d.z), "+f"(d.w)
        : "r"(a.x), "r"(a.y), "r"(a.z), "r"(a.w), "r"(b.x), "r"(b.y));
}

// ================= prep kernel: build g_R =================
__global__ __launch_bounds__(128) void prep_kernel(const float* __restrict__ x) {
    __shared__ float xs[64 * 29];
    const int p = blockIdx.x;            // n*28 + h'
    const int n = p / 28, h = p - n * 28;
    const int tid = threadIdx.x;

    for (int e = tid; e < 64 * 28; e += 128) {
        const int c = e / 28, u = e - c * 28;
        xs[c * 29 + u] = x[(((size_t)n * 64 + c) * 28 + h) * 28 + u];
    }
    __syncthreads();

    float* Rout = g_R + (size_t)p * (32 * 32);
    const int l = tid & 31;
    const int q0 = tid >> 5;
    #pragma unroll
    for (int qq = 0; qq < 8; ++qq) {
        const int q = qq * 4 + q0;
        float v;
        if (q < 28) {
            int u1 = q - 1; if (u1 < 0) u1 += 28;
            int u2 = q - 2; if (u2 < 0) u2 += 28;
            v = xs[l * 29 + u1] + xs[(32 + l) * 29 + u2];
        } else if (q == 28) v = xs[(32 + l) * 29 + 25];   // k=0, w=0
        else if (q == 29)   v = xs[l * 29 + 27];          // k=0, w=1
        else if (q == 30)   v = xs[l * 29 + 0];           // k=2, w=0
        else                v = xs[(32 + l) * 29 + 26];   // k=2, w=27
        Rout[q * 32 + l] = __uint_as_float(f2tf32(v));
    }
}

// ================= main kernel =================
__global__ __launch_bounds__(256, 1) void main_kernel(const float* __restrict__ Wg,
                                                      float* __restrict__ out) {
    extern __shared__ char smem[];
    float*  ws   = reinterpret_cast<float*>(smem + WS_OFF);
    const uint4* ws4 = reinterpret_cast<const uint4*>(smem + WS_OFF);
    float*  act[2] = { reinterpret_cast<float*>(smem + ACT0_OFF),
                       reinterpret_cast<float*>(smem + ACT1_OFF) };
    int*    off9 = reinterpret_cast<int*>(smem + OFF9_OFF);

    const int tid  = threadIdx.x;
    const int lane = tid & 31;
    const int wid  = tid >> 5;
    const int warp_i = wid & 1;     // i-half: ibase = warp_i*64
    const int warp_m = wid >> 1;    // m-quarter: mbase_local = warp_m*32

    // ---- weights -> fragment-ready smem (once per CTA) ----
    // Wg flat e: kko = e>>7 (= l*9 + c), i = e&127; k' = c*32 + l
    for (int e = tid; e < KKT * IIC; e += 256) {
        const int i   = e & 127;
        const int kko = e >> 7;
        const int l   = kko / 9;
        const int c   = kko - l * 9;
        const int kp  = c * 32 + l;
        const int S   = kp >> 3;
        const int kk8 = kp & 7;
        const int mt  = i >> 4;
        const int r   = i & 15;
        const int t   = ((r & 7) << 2) + (kk8 & 3);
        const int reg = (r >> 3) + ((kk8 >> 2) << 1);
        ws[(((S << 3) + mt) * 32 + t) * 4 + reg] = __uint_as_float(f2tf32(Wg[e]));
    }
    __syncthreads();

    for (int g = blockIdx.x; g < NTILES; g += gridDim.x) {
        const int n  = g / TILES_PER_N;
        const int tt = g - n * TILES_PER_N;

        // ---- build off9[c][m] table ----
        for (int e = tid; e < 9 * 128; e += 256) {
            const int c = e >> 7;
            const int m = e & 127;
            const int mg = tt * 128 + m;
            int off = -1;
            if (mg < 784) {
                const int h  = mg / 28;
                const int wp = mg - h * 28;
                const int j  = c / 3;
                const int k  = c - j * 3;
                const int hp = h + j - 1;
                if ((unsigned)hp < 28u) {
                    int idx;
                    if (k == 0)      idx = (wp == 0) ? 28 : (wp == 1) ? 29 : (wp - 1);
                    else if (k == 1) idx = wp;
                    else             idx = (wp == 0) ? 30 : (wp == 27) ? 31 : (wp + 1);
                    off = (((n * 28 + hp) << 5) + idx) << 5;
                }
            }
            off9[e] = off;
        }
        __syncthreads();

        // ---- stage chunk 0 ----
        {
            const int c = 0;
            float* buf = act[0];
            #pragma unroll
            for (int it = 0; it < 4; ++it) {
                const int fidx = it * 256 + tid;       // 0..1023
                const int m  = fidx >> 3;
                const int lq = fidx & 7;
                const int l0 = lq << 2;
                const int off = off9[c * 128 + m];
                float4 v = make_float4(0.f, 0.f, 0.f, 0.f);
                if (off >= 0) v = *reinterpret_cast<const float4*>(g_R + off + l0);
                const float vv[4] = { v.x, v.y, v.z, v.w };
                #pragma unroll
                for (int d = 0; d < 4; ++d) {
                    const int l   = l0 + d;
                    const int sL  = l >> 3;
                    const int kk8 = l & 7;
                    const int t   = ((m & 7) << 2) + (kk8 & 3);
                    const int nt  = m >> 3;
                    const int reg = kk8 >> 2;
                    buf[(((sL << 4) + nt) * 32 + t) * 2 + reg] = vv[d];
                }
            }
        }
        __syncthreads();

        float4 acc[4][4];
        #pragma unroll
        for (int a = 0; a < 4; ++a)
            #pragma unroll
            for (int b = 0; b < 4; ++b)
                acc[a][b] = make_float4(0.f, 0.f, 0.f, 0.f);

        // ---- 9 chunks: stage(c+1) || mma(c) ----
        #pragma unroll 1
        for (int c = 0; c < 9; ++c) {
            if (c < 9 - 1) {
                const int cn = c + 1;
                float* buf = act[cn & 1];
                #pragma unroll
                for (int it = 0; it < 4; ++it) {
                    const int fidx = it * 256 + tid;
                    const int m  = fidx >> 3;
                    const int lq = fidx & 7;
                    const int l0 = lq << 2;
                    const int off = off9[cn * 128 + m];
                    float4 v = make_float4(0.f, 0.f, 0.f, 0.f);
                    if (off >= 0) v = *reinterpret_cast<const float4*>(g_R + off + l0);
                    const float vv[4] = { v.x, v.y, v.z, v.w };
                    #pragma unroll
                    for (int d = 0; d < 4; ++d) {
                        const int l   = l0 + d;
                        const int sL  = l >> 3;
                        const int kk8 = l & 7;
                        const int t   = ((m & 7) << 2) + (kk8 & 3);
                        const int nt  = m >> 3;
                        const int reg = kk8 >> 2;
                        buf[(((sL << 4) + nt) * 32 + t) * 2 + reg] = vv[d];
                    }
                }
            }

            const uint2* b2 = reinterpret_cast<const uint2*>(act[c & 1]);
            #pragma unroll
            for (int s = 0; s < 4; ++s) {
                const int S = c * 4 + s;
                uint4 afr[4];
                #pragma unroll
                for (int mtl = 0; mtl < 4; ++mtl)
                    afr[mtl] = ws4[((S << 3) + (warp_i * 4 + mtl)) * 32 + lane];
                uint2 bfr[4];
                #pragma unroll
                for (int ntl = 0; ntl < 4; ++ntl)
                    bfr[ntl] = b2[((s << 4) + (warp_m * 4 + ntl)) * 32 + lane];
                #pragma unroll
                for (int mtl = 0; mtl < 4; ++mtl)
                    #pragma unroll
                    for (int ntl = 0; ntl < 4; ++ntl)
                        mma_tf32(acc[mtl][ntl], afr[mtl], bfr[ntl]);
            }
            __syncthreads();
        }

        // ---- epilogue: coalesced float2 stores ----
        const size_t outn = (size_t)n * (IIC * 784);
        #pragma unroll
        for (int mtl = 0; mtl < 4; ++mtl) {
            const int i0 = warp_i * 64 + mtl * 16 + (lane >> 2);
            #pragma unroll
            for (int ntl = 0; ntl < 4; ++ntl) {
                const int mloc = warp_m * 32 + ntl * 8 + ((lane & 3) << 1);
                const int mg = tt * 128 + mloc;
                if (mg < 784) {
                    const float4 v = acc[mtl][ntl];
                    *reinterpret_cast<float2*>(out + outn + (size_t)i0 * 784 + mg)
                        = make_float2(v.x, v.y);
                    *reinterpret_cast<float2*>(out + outn + (size_t)(i0 + 8) * 784 + mg)
                        = make_float2(v.z, v.w);
                }
            }
        }
        __syncthreads();   // epilogue/off9 reuse ordering for next tile
    }
}

// ================= launch =================
extern "C" void kernel_launch(void* const* d_in, const int* in_sizes, int n_in,
                              void* d_out, int out_size) {
    const float* x  = (const float*)d_in[0];   // (1024,64,28,28)
    const float* Wg = (const float*)d_in[1];   // (32,3,3,128)
    float* out = (float*)d_out;                // (1024,128,28,28)

    prep_kernel<<<NB * 28, 128>>>(x);

    cudaFuncSetAttribute(main_kernel, cudaFuncAttributeMaxDynamicSharedMemorySize, SM_TOTAL);
    main_kernel<<<GRID_MAIN, 256, SM_TOTAL>>>(Wg, out);
}